// round 2
// baseline (speedup 1.0000x reference)
#include <cuda_runtime.h>

// ---------------------------------------------------------------------------
// PAC transposed conv, fused single kernel.
// out[b,o,h,w] = bias[o] + sum over taps (kh,kw) with (h+kh) odd, (w+kw) odd:
//     kern(b,kh,kw,h,w) * sum_c x[b,c,(h+kh-1)/2,(w+kw-1)/2] * W[c,o,kh,kw]
// kern = exp(-0.5 * sum_g (guide[g, h+kh-1, w+kw-1] - guide[g,h,w])^2), zero-pad guide.
// Out-of-range input taps contribute 0 (handled by zero halo in smem).
// ---------------------------------------------------------------------------

constexpr int Bn = 4, Cn = 64, On = 64, Hn = 128, Wn = 128, GHn = 256, GWn = 256;

// smem: x tile [64][9][33] + rearranged weights [64][9][64]
constexpr int SM_X = Cn * 9 * 33;     // 19008 floats
constexpr int SM_W = Cn * 9 * On;     // 36864 floats
constexpr int SMEM_BYTES = (SM_X + SM_W) * 4;  // 223488 B

__device__ __forceinline__ unsigned long long fma2(unsigned long long a,
                                                   unsigned long long b,
                                                   unsigned long long c) {
    unsigned long long d;
    asm("fma.rn.f32x2 %0, %1, %2, %3;" : "=l"(d) : "l"(a), "l"(b), "l"(c));
    return d;
}
__device__ __forceinline__ unsigned long long pack2(float x) {
    unsigned long long d;
    unsigned r = __float_as_uint(x);
    asm("mov.b64 %0, {%1, %1};" : "=l"(d) : "r"(r));
    return d;
}
__device__ __forceinline__ void unpack2(unsigned long long v, float& lo, float& hi) {
    unsigned a, b;
    asm("mov.b64 {%0, %1}, %2;" : "=r"(a), "=r"(b) : "l"(v));
    lo = __uint_as_float(a);
    hi = __uint_as_float(b);
}

__global__ void __launch_bounds__(512, 1)
pac_fused(const float* __restrict__ x, const float* __restrict__ guide,
          const float* __restrict__ weight, const float* __restrict__ bias,
          float* __restrict__ out)
{
    extern __shared__ float sm[];
    float* xs = sm;            // [c][r][col] : 64 x 9 x 33
    float* ws = sm + SM_X;     // [c][t][o]   : 64 x 9 x 64

    const int tid = threadIdx.x;
    const int bx  = blockIdx.x;
    const int b    = bx >> 6;          // 4 batches
    const int tile = bx & 63;          // 64 tiles per image
    const int qy0 = (tile >> 2) * 8;   // 16 tile rows of 8 quads
    const int qx0 = (tile & 3) * 32;   // 4 tile cols of 32 quads

    // --- stage weights: ws[c][t][o] = weight[c][o][t], t = kh*3+kw
    for (int idx = tid; idx < SM_W; idx += 512) {
        int o = idx & 63;
        int t = (idx >> 6) % 9;
        int c = idx / 576;
        ws[idx] = weight[(c * 64 + o) * 9 + t];
    }
    // --- stage x tile with zero halo (rows qy0..qy0+8, cols qx0..qx0+32)
    const float* xb = x + b * Cn * Hn * Wn;
    for (int idx = tid; idx < SM_X; idx += 512) {
        int col = idx % 33;
        int rc  = idx / 33;
        int r   = rc % 9;
        int c   = rc / 9;
        int gi = qy0 + r, gj = qx0 + col;
        xs[idx] = (gi < Hn && gj < Wn) ? xb[(c * Hn + gi) * Wn + gj] : 0.f;
    }
    __syncthreads();

    const int og  = tid & 7;          // 8 groups of 8 output channels
    const int qg  = tid >> 3;         // 64 quad-groups of 4 consecutive quads
    const int qyl = qg >> 3;          // 0..7
    const int qxl = (qg & 7) * 4;     // 0,4,...,28
    const int oBase = og * 8;

    const float* gb = guide + b * 3 * GHn * GWn;
    float* ob = out + (size_t)(b * On + oBase) * GHn * GWn;

    const int hq  = 2 * (qy0 + qyl);  // even output row of this quad row
    const int wqb = 2 * (qx0 + qxl);  // even output col of quad k=0

    #pragma unroll
    for (int cy = 0; cy < 2; ++cy) {
    #pragma unroll
    for (int cx = 0; cx < 2; ++cx) {
        const int h = hq + cy;

        unsigned long long acc[4][4];
        #pragma unroll
        for (int i = 0; i < 4; ++i)
            #pragma unroll
            for (int k = 0; k < 4; ++k) acc[i][k] = 0ull;

        // valid taps: (h+kh) odd -> kh parity = 1-cy ; same for kw
        #pragma unroll
        for (int kh = 1 - cy; kh < 3; kh += 2) {
        #pragma unroll
        for (int kw = 1 - cx; kw < 3; kw += 2) {
            const int t  = kh * 3 + kw;
            const int di = (cy + kh - 1) >> 1;   // 0 or 1
            const int dj = (cx + kw - 1) >> 1;   // 0 or 1

            // --- kern for the 4 quads of this thread
            float kern[4];
            #pragma unroll
            for (int k = 0; k < 4; ++k) {
                const int w  = wqb + 2 * k + cx;
                const int yy = h + kh - 1;
                const int xx = w + kw - 1;
                const bool inb = ((unsigned)yy < (unsigned)GHn) &
                                 ((unsigned)xx < (unsigned)GWn);
                float s = 0.f;
                #pragma unroll
                for (int g = 0; g < 3; ++g) {
                    float gcv = __ldg(&gb[(g * GHn + h) * GWn + w]);
                    float gnv = inb ? __ldg(&gb[(g * GHn + yy) * GWn + xx]) : 0.f;
                    float d = gnv - gcv;
                    s = fmaf(d, d, s);
                }
                kern[k] = __expf(-0.5f * s);
            }

            // --- 64-deep channel reduction: tmp[o-pair][quad]
            unsigned long long tmp[4][4];
            #pragma unroll
            for (int i = 0; i < 4; ++i)
                #pragma unroll
                for (int k = 0; k < 4; ++k) tmp[i][k] = 0ull;

            const ulonglong2* wp =
                reinterpret_cast<const ulonglong2*>(ws + t * 64 + oBase);
            const float* xq = xs + (qyl + di) * 33 + qxl + dj;

            #pragma unroll 4
            for (int c = 0; c < 64; ++c) {
                ulonglong2 wa = wp[0];
                ulonglong2 wb2 = wp[1];
                unsigned long long wv0 = wa.x,  wv1 = wa.y;
                unsigned long long wv2 = wb2.x, wv3 = wb2.y;
                unsigned long long xv0 = pack2(xq[0]);
                unsigned long long xv1 = pack2(xq[1]);
                unsigned long long xv2 = pack2(xq[2]);
                unsigned long long xv3 = pack2(xq[3]);
                tmp[0][0] = fma2(wv0, xv0, tmp[0][0]);
                tmp[0][1] = fma2(wv0, xv1, tmp[0][1]);
                tmp[0][2] = fma2(wv0, xv2, tmp[0][2]);
                tmp[0][3] = fma2(wv0, xv3, tmp[0][3]);
                tmp[1][0] = fma2(wv1, xv0, tmp[1][0]);
                tmp[1][1] = fma2(wv1, xv1, tmp[1][1]);
                tmp[1][2] = fma2(wv1, xv2, tmp[1][2]);
                tmp[1][3] = fma2(wv1, xv3, tmp[1][3]);
                tmp[2][0] = fma2(wv2, xv0, tmp[2][0]);
                tmp[2][1] = fma2(wv2, xv1, tmp[2][1]);
                tmp[2][2] = fma2(wv2, xv2, tmp[2][2]);
                tmp[2][3] = fma2(wv2, xv3, tmp[2][3]);
                tmp[3][0] = fma2(wv3, xv0, tmp[3][0]);
                tmp[3][1] = fma2(wv3, xv1, tmp[3][1]);
                tmp[3][2] = fma2(wv3, xv2, tmp[3][2]);
                tmp[3][3] = fma2(wv3, xv3, tmp[3][3]);
                wp += 144;   // 576 floats = 144 ulonglong2 per channel
                xq += 297;   // 9*33 floats per channel
            }

            // --- apply gaussian affinity weight per tap
            #pragma unroll
            for (int k = 0; k < 4; ++k) {
                unsigned long long kp = pack2(kern[k]);
                #pragma unroll
                for (int i = 0; i < 4; ++i)
                    acc[i][k] = fma2(tmp[i][k], kp, acc[i][k]);
            }
        }}

        // --- epilogue: bias + store
        #pragma unroll
        for (int i = 0; i < 4; ++i) {
            float blo = __ldg(&bias[oBase + 2 * i]);
            float bhi = __ldg(&bias[oBase + 2 * i + 1]);
            #pragma unroll
            for (int k = 0; k < 4; ++k) {
                float lo, hi;
                unpack2(acc[i][k], lo, hi);
                const int w = wqb + 2 * k + cx;
                ob[(size_t)(2 * i) * GHn * GWn + h * GWn + w]     = lo + blo;
                ob[(size_t)(2 * i + 1) * GHn * GWn + h * GWn + w] = hi + bhi;
            }
        }
    }}
}

extern "C" void kernel_launch(void* const* d_in, const int* in_sizes, int n_in,
                              void* d_out, int out_size) {
    const float* x      = (const float*)d_in[0];
    const float* guide  = (const float*)d_in[1];
    const float* weight = (const float*)d_in[2];
    const float* bias   = (const float*)d_in[3];
    float* out = (float*)d_out;

    cudaFuncSetAttribute(pac_fused, cudaFuncAttributeMaxDynamicSharedMemorySize,
                         SMEM_BYTES);
    // 4 batches * 64 tiles (16 x 4 quad tiles of 8x32 quads) = 256 CTAs
    pac_fused<<<256, 512, SMEM_BYTES>>>(x, guide, weight, bias, out);
}

// round 3
// speedup vs baseline: 1.0452x; 1.0452x over previous
#include <cuda_runtime.h>

// ---------------------------------------------------------------------------
// PAC transposed conv, fused single kernel (R2: 1024 thr, conflict-free weights)
// out[b,o,h,w] = bias[o] + sum over taps (kh,kw) with (h+kh) odd, (w+kw) odd:
//     kern(b,kh,kw,h,w) * sum_c x[b,c,(h+kh-1)/2,(w+kw-1)/2] * W[c,o,kh,kw]
// kern = exp(-0.5 * sum_g (guide[g, h+kh-1, w+kw-1] - guide[g,h,w])^2)
// ---------------------------------------------------------------------------

constexpr int Bn = 4, Cn = 64, On = 64, Hn = 128, Wn = 128, GHn = 256, GWn = 256;

// smem: x tile [64][9][33] + weights [c][t][o] 64x9x64
constexpr int SM_X = Cn * 9 * 33;     // 19008 floats
constexpr int SM_W = Cn * 9 * On;     // 36864 floats
constexpr int SMEM_BYTES = (SM_X + SM_W) * 4;  // 223488 B

__device__ __forceinline__ unsigned long long fma2(unsigned long long a,
                                                   unsigned long long b,
                                                   unsigned long long c) {
    unsigned long long d;
    asm("fma.rn.f32x2 %0, %1, %2, %3;" : "=l"(d) : "l"(a), "l"(b), "l"(c));
    return d;
}
__device__ __forceinline__ unsigned long long pack2(float x) {
    unsigned long long d;
    unsigned r = __float_as_uint(x);
    asm("mov.b64 %0, {%1, %1};" : "=l"(d) : "r"(r));
    return d;
}
__device__ __forceinline__ void unpack2(unsigned long long v, float& lo, float& hi) {
    unsigned a, b;
    asm("mov.b64 {%0, %1}, %2;" : "=r"(a), "=r"(b) : "l"(v));
    lo = __uint_as_float(a);
    hi = __uint_as_float(b);
}

__global__ void __launch_bounds__(1024, 1)
pac_fused(const float* __restrict__ x, const float* __restrict__ guide,
          const float* __restrict__ weight, const float* __restrict__ bias,
          float* __restrict__ out)
{
    extern __shared__ float sm[];
    float* xs = sm;            // [c][r][col] : 64 x 9 x 33
    float* ws = sm + SM_X;     // [c][t][o]   : 64 x 9 x 64

    const int tid = threadIdx.x;
    const int bx  = blockIdx.x;
    const int b    = bx >> 6;          // 4 batches
    const int tile = bx & 63;          // 64 tiles per image
    const int qy0 = (tile >> 2) * 8;   // 16 tile rows of 8 quad-rows
    const int qx0 = (tile & 3) * 32;   // 4 tile cols of 32 quad-cols

    // --- stage weights: ws[c][t][o] = weight[c][o][t], t = kh*3+kw
    for (int idx = tid; idx < SM_W; idx += 1024) {
        int o = idx & 63;
        int t = (idx >> 6) % 9;
        int c = idx / 576;
        ws[idx] = weight[(c * 64 + o) * 9 + t];
    }
    // --- stage x tile with zero halo (rows qy0..qy0+8, cols qx0..qx0+32)
    const float* xb = x + b * Cn * Hn * Wn;
    for (int idx = tid; idx < SM_X; idx += 1024) {
        int col = idx % 33;
        int rc  = idx / 33;
        int r   = rc % 9;
        int c   = rc / 9;
        int gi = qy0 + r, gj = qx0 + col;
        xs[idx] = (gi < Hn && gj < Wn) ? xb[(c * Hn + gi) * Wn + gj] : 0.f;
    }
    __syncthreads();

    // Thread owns o-channels {4og..4og+3} U {32+4og..32+4og+3}  (bank-conflict-
    // free LDS.128: float offsets 4og and 32+4og cover all 32 banks per instr)
    const int og  = tid & 7;
    const int qg  = tid >> 3;          // 128 groups of 2 consecutive quads
    const int qyl = qg >> 4;           // 0..7
    const int qxl = (qg & 15) * 2;     // 0,2,...,30

    const float* gb = guide + b * 3 * GHn * GWn;
    float* outb = out + (size_t)b * On * GHn * GWn;

    const int hq  = 2 * (qy0 + qyl);   // even output row of this quad row
    const int wqb = 2 * (qx0 + qxl);   // even output col of quad k=0

    #pragma unroll
    for (int cy = 0; cy < 2; ++cy) {
    #pragma unroll
    for (int cx = 0; cx < 2; ++cx) {
        const int h = hq + cy;

        unsigned long long acc[4][2];
        #pragma unroll
        for (int p = 0; p < 4; ++p)
            #pragma unroll
            for (int k = 0; k < 2; ++k) acc[p][k] = 0ull;

        // valid taps: (h+kh) odd -> kh parity = 1-cy ; same for kw
        #pragma unroll
        for (int kh = 1 - cy; kh < 3; kh += 2) {
        #pragma unroll
        for (int kw = 1 - cx; kw < 3; kw += 2) {
            const int t  = kh * 3 + kw;
            const int di = (cy + kh - 1) >> 1;   // 0 or 1
            const int dj = (cx + kw - 1) >> 1;   // 0 or 1

            // --- gaussian affinity for the 2 quads of this thread
            float kern[2];
            #pragma unroll
            for (int k = 0; k < 2; ++k) {
                const int w  = wqb + 2 * k + cx;
                const int yy = h + kh - 1;
                const int xx = w + kw - 1;
                const bool inb = ((unsigned)yy < (unsigned)GHn) &
                                 ((unsigned)xx < (unsigned)GWn);
                float s = 0.f;
                #pragma unroll
                for (int g = 0; g < 3; ++g) {
                    float gcv = __ldg(&gb[(g * GHn + h) * GWn + w]);
                    float gnv = inb ? __ldg(&gb[(g * GHn + yy) * GWn + xx]) : 0.f;
                    float d = gnv - gcv;
                    s = fmaf(d, d, s);
                }
                kern[k] = __expf(-0.5f * s);
            }

            // --- 64-deep channel reduction: tmp[o-pair][quad]
            unsigned long long tmp[4][2];
            #pragma unroll
            for (int p = 0; p < 4; ++p)
                #pragma unroll
                for (int k = 0; k < 2; ++k) tmp[p][k] = 0ull;

            const float* wp = ws + t * 64 + 4 * og;
            const float* xq = xs + (qyl + di) * 33 + qxl + dj;

            #pragma unroll 2
            for (int c = 0; c < 64; ++c) {
                ulonglong2 wa = *reinterpret_cast<const ulonglong2*>(wp);
                ulonglong2 wb2 = *reinterpret_cast<const ulonglong2*>(wp + 32);
                unsigned long long xv0 = pack2(xq[0]);
                unsigned long long xv1 = pack2(xq[1]);
                tmp[0][0] = fma2(wa.x,  xv0, tmp[0][0]);
                tmp[0][1] = fma2(wa.x,  xv1, tmp[0][1]);
                tmp[1][0] = fma2(wa.y,  xv0, tmp[1][0]);
                tmp[1][1] = fma2(wa.y,  xv1, tmp[1][1]);
                tmp[2][0] = fma2(wb2.x, xv0, tmp[2][0]);
                tmp[2][1] = fma2(wb2.x, xv1, tmp[2][1]);
                tmp[3][0] = fma2(wb2.y, xv0, tmp[3][0]);
                tmp[3][1] = fma2(wb2.y, xv1, tmp[3][1]);
                wp += 576;   // floats per channel (9 taps * 64 o)
                xq += 297;   // 9*33 floats per channel
            }

            // --- apply gaussian affinity weight per tap
            #pragma unroll
            for (int k = 0; k < 2; ++k) {
                unsigned long long kp = pack2(kern[k]);
                #pragma unroll
                for (int p = 0; p < 4; ++p)
                    acc[p][k] = fma2(tmp[p][k], kp, acc[p][k]);
            }
        }}

        // --- epilogue: bias + store (o-pairs: 4og, 4og+2, 32+4og, 32+4og+2)
        #pragma unroll
        for (int p = 0; p < 4; ++p) {
            const int o0 = (p < 2) ? (4 * og + 2 * p) : (32 + 4 * og + 2 * (p - 2));
            float blo = __ldg(&bias[o0]);
            float bhi = __ldg(&bias[o0 + 1]);
            #pragma unroll
            for (int k = 0; k < 2; ++k) {
                float lo, hi;
                unpack2(acc[p][k], lo, hi);
                const int w = wqb + 2 * k + cx;
                outb[(size_t)o0 * GHn * GWn + h * GWn + w]       = lo + blo;
                outb[(size_t)(o0 + 1) * GHn * GWn + h * GWn + w] = hi + bhi;
            }
        }
    }}
}

extern "C" void kernel_launch(void* const* d_in, const int* in_sizes, int n_in,
                              void* d_out, int out_size) {
    const float* x      = (const float*)d_in[0];
    const float* guide  = (const float*)d_in[1];
    const float* weight = (const float*)d_in[2];
    const float* bias   = (const float*)d_in[3];
    float* out = (float*)d_out;

    cudaFuncSetAttribute(pac_fused, cudaFuncAttributeMaxDynamicSharedMemorySize,
                         SMEM_BYTES);
    // 4 batches * 64 tiles (16 x 4 tiles of 8x32 quads) = 256 CTAs
    pac_fused<<<256, 1024, SMEM_BYTES>>>(x, guide, weight, bias, out);
}

// round 4
// speedup vs baseline: 1.5565x; 1.4892x over previous
#include <cuda_runtime.h>

// ---------------------------------------------------------------------------
// PAC transposed conv, fused (R3: warp-uniform weights, lane-coalesced x/out,
// kern-premultiplied into x so only one accumulator bank is needed).
// out[b,o,h,w] = bias[o] + sum over taps (kh,kw) with (h+kh) odd, (w+kw) odd:
//     kern(b,kh,kw,h,w) * sum_c x[b,c,(h+kh-1)/2,(w+kw-1)/2] * W[c,o,kh,kw]
//   = bias[o] + sum_c sum_t W[c,o,t] * (kern_t * x_t)          (reordered)
// ---------------------------------------------------------------------------

constexpr int Cn = 64, On = 64, Hn = 128, Wn = 128, GHn = 256, GWn = 256;

constexpr int SM_X = Cn * 9 * 33;     // x tile [c][row 9][col 33]
constexpr int SM_W = Cn * 9 * On;     // weights [c][t][o]
constexpr int SMEM_BYTES = (SM_X + SM_W) * 4;  // 223488 B

__device__ __forceinline__ unsigned long long fma2(unsigned long long a,
                                                   unsigned long long b,
                                                   unsigned long long c) {
    unsigned long long d;
    asm("fma.rn.f32x2 %0, %1, %2, %3;" : "=l"(d) : "l"(a), "l"(b), "l"(c));
    return d;
}
__device__ __forceinline__ unsigned long long mul2(unsigned long long a,
                                                   unsigned long long b) {
    unsigned long long d;
    asm("mul.rn.f32x2 %0, %1, %2;" : "=l"(d) : "l"(a), "l"(b));
    return d;
}
__device__ __forceinline__ unsigned long long pack2(float x) {
    unsigned long long d;
    unsigned r = __float_as_uint(x);
    asm("mov.b64 %0, {%1, %1};" : "=l"(d) : "r"(r));
    return d;
}
__device__ __forceinline__ void unpack2(unsigned long long v, float& lo, float& hi) {
    unsigned a, b;
    asm("mov.b64 {%0, %1}, %2;" : "=r"(a), "=r"(b) : "l"(v));
    lo = __uint_as_float(a);
    hi = __uint_as_float(b);
}

__global__ void __launch_bounds__(512, 1)
pac_fused(const float* __restrict__ x, const float* __restrict__ guide,
          const float* __restrict__ weight, const float* __restrict__ bias,
          float* __restrict__ out)
{
    extern __shared__ float sm[];
    float* xs = sm;            // [c][r][col] : 64 x 9 x 33
    float* ws = sm + SM_X;     // [c][t][o]   : 64 x 9 x 64

    const int tid = threadIdx.x;
    const int bx  = blockIdx.x;
    const int b    = bx >> 6;          // 4 batches
    const int tile = bx & 63;          // 64 tiles per image
    const int qy0 = (tile >> 2) * 8;   // quad-row origin (8 rows per tile)
    const int qx0 = (tile & 3) * 32;   // quad-col origin (32 cols per tile)

    // --- stage weights: ws[c][t][o] = weight[c][o][t], t = kh*3+kw
    for (int idx = tid; idx < SM_W; idx += 512) {
        int o = idx & 63;
        int t = (idx >> 6) % 9;
        int c = idx / 576;
        ws[idx] = weight[(c * 64 + o) * 9 + t];
    }
    // --- stage x tile with zero halo (rows qy0..qy0+8, cols qx0..qx0+32)
    const float* xb = x + b * Cn * Hn * Wn;
    for (int idx = tid; idx < SM_X; idx += 512) {
        int col = idx % 33;
        int rc  = idx / 33;
        int r   = rc % 9;
        int c   = rc / 9;
        int gi = qy0 + r, gj = qx0 + col;
        xs[idx] = (gi < Hn && gj < Wn) ? xb[(c * Hn + gi) * Wn + gj] : 0.f;
    }
    __syncthreads();

    // warp layout: og = o-group (8 channels, uniform weight addresses per warp)
    //              half selects quad-rows rb..rb+3 ; lane = quad column
    const int wid  = tid >> 5;
    const int lane = tid & 31;
    const int og   = wid & 7;          // o-channels 8og..8og+7
    const int rb   = (wid >> 3) * 4;   // quad rows rb..rb+3 of the tile

    const float* gb = guide + b * 3 * GHn * GWn;
    float* outb = out + (size_t)b * On * GHn * GWn;

    const int wq = 2 * (qx0 + lane);   // even output col for this lane

    #pragma unroll
    for (int cy = 0; cy < 2; ++cy) {
    #pragma unroll
    for (int cx = 0; cx < 2; ++cx) {
        const int w = wq + cx;

        // --- gaussian affinity for all valid taps of this (cy,cx), 4 rows
        float kern[4][4];
        {
            int tapi = 0;
            #pragma unroll
            for (int kh = 1 - cy; kh < 3; kh += 2) {
            #pragma unroll
            for (int kw = 1 - cx; kw < 3; kw += 2) {
                #pragma unroll
                for (int j = 0; j < 4; ++j) {
                    const int h  = 2 * (qy0 + rb + j) + cy;
                    const int yy = h + kh - 1;
                    const int xx = w + kw - 1;
                    const bool inb = ((unsigned)yy < (unsigned)GHn) &
                                     ((unsigned)xx < (unsigned)GWn);
                    float s = 0.f;
                    #pragma unroll
                    for (int g = 0; g < 3; ++g) {
                        float gcv = __ldg(&gb[(g * GHn + h) * GWn + w]);
                        float gnv = inb ? __ldg(&gb[(g * GHn + yy) * GWn + xx]) : 0.f;
                        float d = gnv - gcv;
                        s = fmaf(d, d, s);
                    }
                    kern[tapi][j] = __expf(-0.5f * s);
                }
                ++tapi;
            }}
        }

        // --- accumulate over taps and channels: acc[opair][row]
        unsigned long long acc[4][4];
        #pragma unroll
        for (int p = 0; p < 4; ++p)
            #pragma unroll
            for (int j = 0; j < 4; ++j) acc[p][j] = 0ull;

        {
            int tapi = 0;
            #pragma unroll
            for (int kh = 1 - cy; kh < 3; kh += 2) {
            #pragma unroll
            for (int kw = 1 - cx; kw < 3; kw += 2) {
                const int t  = kh * 3 + kw;
                const int di = (cy + kh - 1) >> 1;
                const int dj = (cx + kw - 1) >> 1;

                unsigned long long kp[4];
                #pragma unroll
                for (int j = 0; j < 4; ++j) kp[j] = pack2(kern[tapi][j]);

                const float* wp = ws + t * 64 + 8 * og;   // uniform per warp
                const float* xp = xs + (rb + di) * 33 + lane + dj;

                #pragma unroll 2
                for (int c = 0; c < 64; ++c) {
                    ulonglong2 wa  = *reinterpret_cast<const ulonglong2*>(wp);
                    ulonglong2 wb2 = *reinterpret_cast<const ulonglong2*>(wp + 4);
                    unsigned long long z0 = mul2(kp[0], pack2(xp[0]));
                    unsigned long long z1 = mul2(kp[1], pack2(xp[33]));
                    unsigned long long z2 = mul2(kp[2], pack2(xp[66]));
                    unsigned long long z3 = mul2(kp[3], pack2(xp[99]));
                    acc[0][0] = fma2(wa.x,  z0, acc[0][0]);
                    acc[0][1] = fma2(wa.x,  z1, acc[0][1]);
                    acc[0][2] = fma2(wa.x,  z2, acc[0][2]);
                    acc[0][3] = fma2(wa.x,  z3, acc[0][3]);
                    acc[1][0] = fma2(wa.y,  z0, acc[1][0]);
                    acc[1][1] = fma2(wa.y,  z1, acc[1][1]);
                    acc[1][2] = fma2(wa.y,  z2, acc[1][2]);
                    acc[1][3] = fma2(wa.y,  z3, acc[1][3]);
                    acc[2][0] = fma2(wb2.x, z0, acc[2][0]);
                    acc[2][1] = fma2(wb2.x, z1, acc[2][1]);
                    acc[2][2] = fma2(wb2.x, z2, acc[2][2]);
                    acc[2][3] = fma2(wb2.x, z3, acc[2][3]);
                    acc[3][0] = fma2(wb2.y, z0, acc[3][0]);
                    acc[3][1] = fma2(wb2.y, z1, acc[3][1]);
                    acc[3][2] = fma2(wb2.y, z2, acc[3][2]);
                    acc[3][3] = fma2(wb2.y, z3, acc[3][3]);
                    wp += 576;   // 9 taps * 64 o per channel
                    xp += 297;   // 9*33 per channel
                }
                ++tapi;
            }}
        }

        // --- epilogue: bias + coalesced store (lanes -> consecutive w)
        #pragma unroll
        for (int p = 0; p < 4; ++p) {
            const int o0 = 8 * og + 2 * p;
            const float blo = __ldg(&bias[o0]);
            const float bhi = __ldg(&bias[o0 + 1]);
            #pragma unroll
            for (int j = 0; j < 4; ++j) {
                const int h = 2 * (qy0 + rb + j) + cy;
                float lo, hi;
                unpack2(acc[p][j], lo, hi);
                outb[(size_t)o0 * GHn * GWn + h * GWn + w]       = lo + blo;
                outb[(size_t)(o0 + 1) * GHn * GWn + h * GWn + w] = hi + bhi;
            }
        }
    }}
}

extern "C" void kernel_launch(void* const* d_in, const int* in_sizes, int n_in,
                              void* d_out, int out_size) {
    const float* x      = (const float*)d_in[0];
    const float* guide  = (const float*)d_in[1];
    const float* weight = (const float*)d_in[2];
    const float* bias   = (const float*)d_in[3];
    float* out = (float*)d_out;

    cudaFuncSetAttribute(pac_fused, cudaFuncAttributeMaxDynamicSharedMemorySize,
                         SMEM_BYTES);
    // 4 batches * 64 tiles (8x32 quads each) = 256 CTAs
    pac_fused<<<256, 512, SMEM_BYTES>>>(x, guide, weight, bias, out);
}

// round 5
// speedup vs baseline: 1.8675x; 1.1998x over previous
#include <cuda_runtime.h>

// ---------------------------------------------------------------------------
// PAC transposed conv, fused (R4: tmp-then-fold kern apply + SW-pipelined LDS)
// out[b,o,h,w] = bias[o] + sum over taps (kh,kw) with (h+kh) odd, (w+kw) odd:
//     kern(b,kh,kw,h,w) * sum_c x[b,c,(h+kh-1)/2,(w+kw-1)/2] * W[c,o,kh,kw]
// Per tap: tmp[o] = sum_c W[c,o,t] * x_t[c]   (64-deep, FFMA2 only)
// then     acc[o] += kern_t * tmp[o]          (one fold per tap)
// ---------------------------------------------------------------------------

constexpr int Cn = 64, On = 64, Hn = 128, Wn = 128, GHn = 256, GWn = 256;

constexpr int SM_X = Cn * 9 * 33;     // x tile [c][row 9][col 33] = 19008
constexpr int SM_W = Cn * 9 * On;     // weights [c][t][o]         = 36864
constexpr int SM_PAD = 640;           // prefetch-overrun pad
constexpr int SMEM_BYTES = (SM_X + SM_W + SM_PAD) * 4;  // 226048 B

__device__ __forceinline__ unsigned long long fma2(unsigned long long a,
                                                   unsigned long long b,
                                                   unsigned long long c) {
    unsigned long long d;
    asm("fma.rn.f32x2 %0, %1, %2, %3;" : "=l"(d) : "l"(a), "l"(b), "l"(c));
    return d;
}
__device__ __forceinline__ unsigned long long pack2(float x) {
    unsigned long long d;
    unsigned r = __float_as_uint(x);
    asm("mov.b64 %0, {%1, %1};" : "=l"(d) : "r"(r));
    return d;
}
__device__ __forceinline__ void unpack2(unsigned long long v, float& lo, float& hi) {
    unsigned a, b;
    asm("mov.b64 {%0, %1}, %2;" : "=r"(a), "=r"(b) : "l"(v));
    lo = __uint_as_float(a);
    hi = __uint_as_float(b);
}

__global__ void __launch_bounds__(512, 1)
pac_fused(const float* __restrict__ x, const float* __restrict__ guide,
          const float* __restrict__ weight, const float* __restrict__ bias,
          float* __restrict__ out)
{
    extern __shared__ float sm[];
    float* xs = sm;            // [c][r][col] : 64 x 9 x 33
    float* ws = sm + SM_X;     // [c][t][o]   : 64 x 9 x 64

    const int tid = threadIdx.x;
    const int bx  = blockIdx.x;
    const int b    = bx >> 6;          // 4 batches
    const int tile = bx & 63;          // 64 tiles per image
    const int qy0 = (tile >> 2) * 8;   // quad-row origin
    const int qx0 = (tile & 3) * 32;   // quad-col origin

    // --- stage weights: ws[c][t][o] = weight[c][o][t], t = kh*3+kw
    for (int idx = tid; idx < SM_W; idx += 512) {
        int o = idx & 63;
        int t = (idx >> 6) % 9;
        int c = idx / 576;
        ws[idx] = weight[(c * 64 + o) * 9 + t];
    }
    // --- stage x tile with zero halo
    const float* xb = x + b * Cn * Hn * Wn;
    for (int idx = tid; idx < SM_X; idx += 512) {
        int col = idx % 33;
        int rc  = idx / 33;
        int r   = rc % 9;
        int c   = rc / 9;
        int gi = qy0 + r, gj = qx0 + col;
        xs[idx] = (gi < Hn && gj < Wn) ? xb[(c * Hn + gi) * Wn + gj] : 0.f;
    }
    __syncthreads();

    // warp layout: og = o-group (8 channels, uniform weight addr per warp);
    // rb selects 4 quad-rows; lane = quad column (coalesced x / out).
    const int wid  = tid >> 5;
    const int lane = tid & 31;
    const int og   = wid & 7;          // o-channels 8og..8og+7
    const int rb   = (wid >> 3) * 4;   // quad rows rb..rb+3

    const float* gb = guide + b * 3 * GHn * GWn;
    float* outb = out + (size_t)b * On * GHn * GWn;

    const int wq = 2 * (qx0 + lane);

    #pragma unroll
    for (int cy = 0; cy < 2; ++cy) {
    #pragma unroll
    for (int cx = 0; cx < 2; ++cx) {
        const int w = wq + cx;

        // hoisted center-guide values for the 4 rows
        float gcv[4][3];
        #pragma unroll
        for (int j = 0; j < 4; ++j) {
            const int h = 2 * (qy0 + rb + j) + cy;
            #pragma unroll
            for (int g = 0; g < 3; ++g)
                gcv[j][g] = __ldg(&gb[(g * GHn + h) * GWn + w]);
        }

        unsigned long long acc[4][4];
        #pragma unroll
        for (int p = 0; p < 4; ++p)
            #pragma unroll
            for (int j = 0; j < 4; ++j) acc[p][j] = 0ull;

        #pragma unroll
        for (int kh = 1 - cy; kh < 3; kh += 2) {
        #pragma unroll
        for (int kw = 1 - cx; kw < 3; kw += 2) {
            const int t  = kh * 3 + kw;
            const int di = (cy + kh - 1) >> 1;
            const int dj = (cx + kw - 1) >> 1;

            // kern for 4 rows — issued before c-loop, consumed after it
            float kern[4];
            #pragma unroll
            for (int j = 0; j < 4; ++j) {
                const int h  = 2 * (qy0 + rb + j) + cy;
                const int yy = h + kh - 1;
                const int xx = w + kw - 1;
                const bool inb = ((unsigned)yy < (unsigned)GHn) &
                                 ((unsigned)xx < (unsigned)GWn);
                float s = 0.f;
                #pragma unroll
                for (int g = 0; g < 3; ++g) {
                    float gnv = inb ? __ldg(&gb[(g * GHn + yy) * GWn + xx]) : 0.f;
                    float d = gnv - gcv[j][g];
                    s = fmaf(d, d, s);
                }
                kern[j] = __expf(-0.5f * s);
            }

            unsigned long long tmp[4][4];
            #pragma unroll
            for (int p = 0; p < 4; ++p)
                #pragma unroll
                for (int j = 0; j < 4; ++j) tmp[p][j] = 0ull;

            const float* wp = ws + t * 64 + 8 * og;   // uniform per warp
            const float* xp = xs + (rb + di) * 33 + lane + dj;

            // software pipeline: values for iter c loaded at iter c-1
            ulonglong2 wa  = *reinterpret_cast<const ulonglong2*>(wp);
            ulonglong2 wb2 = *reinterpret_cast<const ulonglong2*>(wp + 4);
            float x0 = xp[0], x1 = xp[33], x2 = xp[66], x3 = xp[99];

            #pragma unroll 4
            for (int c = 0; c < 64; ++c) {
                wp += 576;   // 9 taps * 64 o per channel
                xp += 297;   // 9*33 per channel
                // prefetch next channel (one-past-end lands in smem pad)
                ulonglong2 wan = *reinterpret_cast<const ulonglong2*>(wp);
                ulonglong2 wbn = *reinterpret_cast<const ulonglong2*>(wp + 4);
                float xn0 = xp[0], xn1 = xp[33], xn2 = xp[66], xn3 = xp[99];

                unsigned long long z0 = pack2(x0);
                unsigned long long z1 = pack2(x1);
                unsigned long long z2 = pack2(x2);
                unsigned long long z3 = pack2(x3);
                tmp[0][0] = fma2(wa.x,  z0, tmp[0][0]);
                tmp[0][1] = fma2(wa.x,  z1, tmp[0][1]);
                tmp[0][2] = fma2(wa.x,  z2, tmp[0][2]);
                tmp[0][3] = fma2(wa.x,  z3, tmp[0][3]);
                tmp[1][0] = fma2(wa.y,  z0, tmp[1][0]);
                tmp[1][1] = fma2(wa.y,  z1, tmp[1][1]);
                tmp[1][2] = fma2(wa.y,  z2, tmp[1][2]);
                tmp[1][3] = fma2(wa.y,  z3, tmp[1][3]);
                tmp[2][0] = fma2(wb2.x, z0, tmp[2][0]);
                tmp[2][1] = fma2(wb2.x, z1, tmp[2][1]);
                tmp[2][2] = fma2(wb2.x, z2, tmp[2][2]);
                tmp[2][3] = fma2(wb2.x, z3, tmp[2][3]);
                tmp[3][0] = fma2(wb2.y, z0, tmp[3][0]);
                tmp[3][1] = fma2(wb2.y, z1, tmp[3][1]);
                tmp[3][2] = fma2(wb2.y, z2, tmp[3][2]);
                tmp[3][3] = fma2(wb2.y, z3, tmp[3][3]);

                wa = wan; wb2 = wbn;
                x0 = xn0; x1 = xn1; x2 = xn2; x3 = xn3;
            }

            // fold: acc += kern_t * tmp   (once per tap)
            #pragma unroll
            for (int j = 0; j < 4; ++j) {
                unsigned long long kp = pack2(kern[j]);
                #pragma unroll
                for (int p = 0; p < 4; ++p)
                    acc[p][j] = fma2(tmp[p][j], kp, acc[p][j]);
            }
        }}

        // --- epilogue: bias + coalesced store
        #pragma unroll
        for (int p = 0; p < 4; ++p) {
            const int o0 = 8 * og + 2 * p;
            const float blo = __ldg(&bias[o0]);
            const float bhi = __ldg(&bias[o0 + 1]);
            #pragma unroll
            for (int j = 0; j < 4; ++j) {
                const int h = 2 * (qy0 + rb + j) + cy;
                float lo, hi;
                unpack2(acc[p][j], lo, hi);
                outb[(size_t)o0 * GHn * GWn + h * GWn + w]       = lo + blo;
                outb[(size_t)(o0 + 1) * GHn * GWn + h * GWn + w] = hi + bhi;
            }
        }
    }}
}

extern "C" void kernel_launch(void* const* d_in, const int* in_sizes, int n_in,
                              void* d_out, int out_size) {
    const float* x      = (const float*)d_in[0];
    const float* guide  = (const float*)d_in[1];
    const float* weight = (const float*)d_in[2];
    const float* bias   = (const float*)d_in[3];
    float* out = (float*)d_out;

    cudaFuncSetAttribute(pac_fused, cudaFuncAttributeMaxDynamicSharedMemorySize,
                         SMEM_BYTES);
    // 4 batches * 64 tiles (8x32 quads each) = 256 CTAs
    pac_fused<<<256, 512, SMEM_BYTES>>>(x, guide, weight, bias, out);
}